// round 17
// baseline (speedup 1.0000x reference)
#include <cuda_runtime.h>

#define NN 8192
#define MM 2048
#define DD 256
#define DHH 8
#define ROW_CAP 64
#define SEG_CAP 32
#define PROJ_BLOCKS 40          // (NN+MM)/256
#define SCAN_BLOCKS 2048        // 16384 warps, one per H half-row
#define UPL 8                   // uint4 per lane (256 per half-row / 32 lanes)

// ---------------- scratch (static device globals; zero-init at load) ---------
__device__ float g_sx[NN];
__device__ float g_s2[NN];
__device__ __align__(8)  float2 g_sepack[MM];       // (se, s1)
__device__ __align__(8)  int2  g_row_cnt2[NN];      // per-half counts; overwritten each replay
__device__ __align__(16) int g_row_edges[NN * ROW_CAP];  // two 32-slot segments per row
__device__ __align__(16) float g_wx[NN * DHH];      // projected X rows
__device__ __align__(16) float g_eacc[MM * DHH];    // zeroed by k_main proj (same replay)
__device__ float g_colsum[MM];                      // zeroed by k_main proj (same replay)
__device__ __align__(16) float g_empty_wx[DHH];     // zeroed by k_main proj

__device__ __forceinline__ float leaky(float x) { return x >= 0.f ? x : 0.2f * x; }
// fast ELU: __expf(x)-1 (~6e-8 abs err vs expm1f; global tol is 1e-3)
__device__ __forceinline__ float elu(float x)   { return x > 0.f ? x : __expf(x) - 1.f; }
__device__ __forceinline__ void pdl_wait()    { asm volatile("griddepcontrol.wait;" ::: "memory"); }
__device__ __forceinline__ void pdl_trigger() { asm volatile("griddepcontrol.launch_dependents;" ::: "memory"); }
__device__ __forceinline__ void red_add_v4(float* p, float a, float b, float c, float d) {
    asm volatile("red.global.add.v4.f32 [%0], {%1, %2, %3, %4};"
                 :: "l"(p), "f"(a), "f"(b), "f"(c), "f"(d) : "memory");
}

// map list position j -> flat index into g_row_edges for segmented lists
__device__ __forceinline__ int seg_idx(int row, int j, int c0) {
    return row * ROW_CAP + ((j < c0) ? j : (SEG_CAP + j - c0));
}

// process one uint4 (4 H entries) for the warp-per-half-row scan
__device__ __forceinline__ void scan_u4(uint4 h, int q, int lane, int base_slot_addr,
                                        int colbase, int& cnt) {
    unsigned nz = (h.x ? 1u : 0u) | (h.y ? 2u : 0u) | (h.z ? 4u : 0u) | (h.w ? 8u : 0u);
    int nl = __popc(nz);
    unsigned bal = __ballot_sync(0xffffffffu, nz != 0u);
    if (bal) {                                  // warp-uniform branch
        int off = nl;                           // inclusive prefix over lanes
#pragma unroll
        for (int d = 1; d < 32; d <<= 1) {
            int v = __shfl_up_sync(0xffffffffu, off, d);
            if (lane >= d) off += v;
        }
        int slot = cnt + off - nl;
        int colb = colbase + (q * 32 + lane) * 4;
#pragma unroll
        for (int c = 0; c < 4; c++) {
            if ((nz >> c) & 1u) {
                if (slot < SEG_CAP) g_row_edges[base_slot_addr + slot] = colb + c;
                slot++;
            }
        }
        cnt += __shfl_sync(0xffffffffu, off, 31);
    }
}

// ---------------- K1: fused projection + atomic-free H scan ------------------
__global__ void __launch_bounds__(256, 4) k_main(
        const float* __restrict__ X, const float* __restrict__ E,
        const float* __restrict__ H, const float* __restrict__ W,
        const float* __restrict__ ax, const float* __restrict__ ae) {
    if (blockIdx.x >= PROJ_BLOCKS) {
        // ---- scan: warp per HALF-row; loads pre-wait; writes post-wait ----
        int wg   = (blockIdx.x - PROJ_BLOCKS) * 8 + (threadIdx.x >> 5);  // 0..16383
        int row  = wg >> 1;
        int half = wg & 1;
        int lane = threadIdx.x & 31;
        const uint4* Hp = reinterpret_cast<const uint4*>(H) + (size_t)row * 512 + half * 256;

        uint4 v[UPL];
#pragma unroll
        for (int q = 0; q < UPL; q++) v[q] = Hp[q * 32 + lane];   // pre-wait batch

        pdl_wait();        // prior replay's k_final done reading row lists
        pdl_trigger();     // k_mid may prelaunch

        int cnt = 0;
        int base = row * ROW_CAP + half * SEG_CAP;
        int colbase = half * 1024;
#pragma unroll
        for (int q = 0; q < UPL; q++) scan_u4(v[q], q, lane, base, colbase, cnt);

        if (lane == 0) {
            int c = min(cnt, SEG_CAP);
            if (half == 0) g_row_cnt2[row].x = c;
            else           g_row_cnt2[row].y = c;
        }
        return;
    }

    // ---- projection: full compute PRE-wait (inputs only) ----
    __shared__ float sW[DD * DHH];
    __shared__ float sax[2 * DHH], sae[2 * DHH];
    for (int j = threadIdx.x; j < DD * DHH; j += blockDim.x) sW[j] = W[j];
    if (threadIdx.x < 2 * DHH) {
        sax[threadIdx.x] = ax[threadIdx.x];
        sae[threadIdx.x] = ae[threadIdx.x];
    }
    __syncthreads();

    int r = blockIdx.x * blockDim.x + threadIdx.x;   // 0..10239
    const float* src = (r < NN) ? (X + (size_t)r * DD)
                                : (E + (size_t)(r - NN) * DD);
    float acc[DHH];
#pragma unroll
    for (int d = 0; d < DHH; d++) acc[d] = 0.f;

    const float4* Ar = reinterpret_cast<const float4*>(src);
#pragma unroll 4
    for (int j4 = 0; j4 < DD / 4; j4++) {
        float4 x = Ar[j4];
        int j = 4 * j4;
#pragma unroll
        for (int d = 0; d < DHH; d++) acc[d] += x.x * sW[(j + 0) * DHH + d];
#pragma unroll
        for (int d = 0; d < DHH; d++) acc[d] += x.y * sW[(j + 1) * DHH + d];
#pragma unroll
        for (int d = 0; d < DHH; d++) acc[d] += x.z * sW[(j + 2) * DHH + d];
#pragma unroll
        for (int d = 0; d < DHH; d++) acc[d] += x.w * sW[(j + 3) * DHH + d];
    }
    float d1 = 0.f, d2 = 0.f;
    if (r < NN) {
#pragma unroll
        for (int d = 0; d < DHH; d++) {
            d1 += acc[d] * sax[d];          // alpha_x[:dh]
            d2 += acc[d] * sae[DHH + d];    // alpha_e[dh:]
        }
    } else {
#pragma unroll
        for (int d = 0; d < DHH; d++) {
            d1 += acc[d] * sax[DHH + d];    // alpha_x[dh:]
            d2 += acc[d] * sae[d];          // alpha_e[:dh]
        }
    }

    pdl_wait();        // prior replay fully done -> safe to overwrite state
    pdl_trigger();

    // zero same-replay accumulators (consumed by prior replay's k_final)
    if (r < MM * DHH / 4)
        reinterpret_cast<float4*>(g_eacc)[r] = make_float4(0.f, 0.f, 0.f, 0.f);
    if (r < MM / 4)
        reinterpret_cast<float4*>(g_colsum)[r] = make_float4(0.f, 0.f, 0.f, 0.f);
    if (r < DHH) g_empty_wx[r] = 0.f;

    if (r < NN) {
        g_sx[r] = d1; g_s2[r] = d2;
        float4* wp = reinterpret_cast<float4*>(&g_wx[r * DHH]);
        wp[0] = make_float4(acc[0], acc[1], acc[2], acc[3]);
        wp[1] = make_float4(acc[4], acc[5], acc[6], acc[7]);
    } else {
        g_sepack[r - NN] = make_float2(d1, d2);      // (se, s1)
    }
}

// ---------------- K2: per-node rowSum + eacc/colsum scatter (8 lanes/node) ---
__global__ void __launch_bounds__(256) k_mid() {
    pdl_wait();        // k_main done: lists/proj final, eacc/colsum zeroed
    pdl_trigger();     // k_final may prelaunch (its pre-wait reads k_main data only)

    int gid = blockIdx.x * blockDim.x + threadIdx.x;   // NN*8 threads
    int i = gid >> 3, l8 = gid & 7;
    int2 c2 = g_row_cnt2[i];
    int c0 = c2.x, cnt = c2.x + c2.y;
    float sxi = g_sx[i], s2i = g_s2[i];

    int   idx[8];
    float e1[8], e2[8];
    float s = 0.f;
#pragma unroll
    for (int t = 0; t < 8; t++) {
        int j = l8 + 8 * t;
        bool act = (j < cnt);
        int k = act ? g_row_edges[seg_idx(i, j, c0)] : 0;
        float2 ss = g_sepack[k];
        idx[t] = act ? k : -1;
        e1[t] = act ? __expf(leaky(sxi + ss.x)) : 0.f;
        e2[t] = act ? __expf(leaky(ss.y + s2i)) : 0.f;
        s += e1[t];
    }
    // width-8 butterfly, UNCONDITIONAL
    s += __shfl_xor_sync(0xffffffffu, s, 4);
    s += __shfl_xor_sync(0xffffffffu, s, 2);
    s += __shfl_xor_sync(0xffffffffu, s, 1);

    if (cnt == 0) {
        if (l8 == 0) {
            const float4* w = reinterpret_cast<const float4*>(&g_wx[i * DHH]);
            float4 w0 = w[0], w1 = w[1];
            red_add_v4(&g_empty_wx[0], w0.x, w0.y, w0.z, w0.w);
            red_add_v4(&g_empty_wx[4], w1.x, w1.y, w1.z, w1.w);
        }
        return;
    }

    float inv = 1.f / s;
    const float4* w = reinterpret_cast<const float4*>(&g_wx[i * DHH]);
    float4 w0 = w[0], w1 = w[1];
#pragma unroll
    for (int t = 0; t < 8; t++) {
        if (idx[t] >= 0) {
            float ww = e1[t] * inv;
            float* dst = &g_eacc[idx[t] * DHH];
            red_add_v4(dst,     ww * w0.x, ww * w0.y, ww * w0.z, ww * w0.w);
            red_add_v4(dst + 4, ww * w1.x, ww * w1.y, ww * w1.z, ww * w1.w);
            atomicAdd(&g_colsum[idx[t]], e2[t]);     // no-return -> REDG
        }
    }
}

// ---------------- K3: X_new node-gather (8 lanes/node, lane=dim) -------------
__global__ void __launch_bounds__(256) k_final(float* __restrict__ out) {
    int gid = blockIdx.x * blockDim.x + threadIdx.x;   // NN*8 threads
    int i = gid >> 3, u = gid & 7;
    int2 c2 = g_row_cnt2[i];
    int c0 = c2.x, cnt = c2.x + c2.y;
    float s2i = g_s2[i];
    int   kt[16];
    float e2[16];
#pragma unroll
    for (int t = 0; t < 16; t++)
        kt[t] = (t < cnt) ? g_row_edges[seg_idx(i, t, c0)] : -1;
#pragma unroll
    for (int t = 0; t < 16; t++)
        e2[t] = (kt[t] >= 0) ? __expf(leaky(g_sepack[kt[t]].y + s2i)) : 0.f;

    pdl_wait();        // k_mid done: eacc/colsum/empty_wx final
    pdl_trigger();     // next replay's k_main may prelaunch (H loads overlap us)

    const float invM = 1.f / MM;
    float ewu = invM * g_empty_wx[u];
    float acc = 0.f;

    float cs[16], ea[16];
#pragma unroll
    for (int t = 0; t < 16; t++) {
        int k = (kt[t] >= 0) ? kt[t] : 0;
        cs[t] = g_colsum[k];
        ea[t] = g_eacc[k * DHH + u];       // coalesced 32B across the 8-lane group
    }
#pragma unroll
    for (int t = 0; t < 16; t++)
        if (kt[t] >= 0 && cs[t] > 0.f)
            acc += __fdividef(e2[t], cs[t]) * elu(ea[t] + ewu);

    // rare tail (cnt > 16)
    for (int t = 16; t < cnt; t++) {
        int k = g_row_edges[seg_idx(i, t, c0)];
        float e = __expf(leaky(g_sepack[k].y + s2i));
        float c = g_colsum[k];
        if (c > 0.f) acc += __fdividef(e, c) * elu(g_eacc[k * DHH + u] + ewu);
    }

    out[i * DHH + u] = elu(acc);
}

// -----------------------------------------------------------------------------
extern "C" void kernel_launch(void* const* d_in, const int* in_sizes, int n_in,
                              void* d_out, int out_size) {
    const float* X  = (const float*)d_in[0];
    const float* E  = (const float*)d_in[1];
    const float* H  = (const float*)d_in[2];
    const float* W  = (const float*)d_in[3];
    const float* ax = (const float*)d_in[4];
    const float* ae = (const float*)d_in[5];
    float* out = (float*)d_out;

    cudaLaunchAttribute attr;
    attr.id = cudaLaunchAttributeProgrammaticStreamSerialization;
    attr.val.programmaticStreamSerializationAllowed = 1;

    cudaLaunchConfig_t cfg = {};
    cfg.blockDim = dim3(256);
    cfg.dynamicSmemBytes = 0;
    cfg.stream = 0;
    cfg.attrs = &attr;
    cfg.numAttrs = 1;

    cfg.gridDim = dim3(PROJ_BLOCKS + SCAN_BLOCKS);
    cudaLaunchKernelEx(&cfg, k_main, X, E, H, W, ax, ae);

    cfg.gridDim = dim3(NN * 8 / 256);
    cudaLaunchKernelEx(&cfg, k_mid);

    cfg.gridDim = dim3(NN * 8 / 256);
    cudaLaunchKernelEx(&cfg, k_final, out);
}